// round 12
// baseline (speedup 1.0000x reference)
#include <cuda_runtime.h>

// net_LSTM_21534966022336: T=4096, B=8192, I=H=1 -> 8192 independent scalar
// LSTM chains. R8 locked the single-chain optimum at ~101 cyc/step
// (= 2L + K, L~39 eff MUFU RAW, K~23). Hypothesis: L - 16 = warp
// sleep/wakeup overhead at each scoreboard wait, NOT dataflow. This round
// interleaves TWO independent chains per thread (b and b+B/2): chain B's
// instruction stream fills chain A's MUFU waits, so waits resolve
// pre-drained and both chains advance one step per ~64 cyc
// (MUFU-port floor: 8 tanh x rt 8).

#ifndef LSTM_T
#define LSTM_T 4096
#endif
#ifndef LSTM_B
#define LSTM_B 8192
#endif

__device__ __forceinline__ float tanh_approx(float v) {
    float y;
    asm("tanh.approx.f32 %0, %1;" : "=f"(y) : "f"(v));
    return y;
}

__global__ void __launch_bounds__(128, 1)
lstm_scalar_chain_kernel(const float* __restrict__ x,
                         const float* __restrict__ h0,
                         const float* __restrict__ c0,
                         const float* __restrict__ w_ih,
                         const float* __restrict__ w_hh,
                         float* __restrict__ out,
                         int out_size) {
    const int b = blockIdx.x * blockDim.x + threadIdx.x;
    constexpr int HB = LSTM_B / 2;
    if (b >= HB) return;

    // Pre-scaled shared scalar weights (gate order i, f, g, o).
    const float wi_i = 0.50f * w_ih[0];
    const float wi_f = 0.50f * w_ih[1];
    const float wi_g =         w_ih[2];
    const float wi_o = 0.50f * w_ih[3];
    const float wh_i = 0.25f * w_hh[0];
    const float wh_f = 0.25f * w_hh[1];
    const float wh_g = 0.50f * w_hh[2];
    const float wh_o = 0.25f * w_hh[3];

    // Two independent chains: A = b, B = b + HB.
    // Seed: tc*(1+to) = 2*h0 -> tc = 2*h0, to = 0 (exact).
    float tcA = 2.0f * h0[b],      toA = 0.0f, cA = c0[b],      hpA = 0.0f;
    float tcB = 2.0f * h0[b + HB], toB = 0.0f, cB = c0[b + HB], hpB = 0.0f;

    const float* xpA = x + b;
    const float* xpB = x + b + HB;
    float*       opA = out + b;
    float*       opB = out + b + HB;

    // 4-phase ring of 8-wide x buffers per chain, reloaded in place.
    float xrA[32], xrB[32];
#pragma unroll
    for (int u = 0; u < 32; ++u) xrA[u] = xpA[u * LSTM_B];
#pragma unroll
    for (int u = 0; u < 32; ++u) xrB[u] = xpB[u * LSTM_B];

    // One LSTM step (R5/R8 dataflow) for one chain; store pipelined by 1 step.
#define LSTM_STEP(tc, to, c, hp, xv, op, t_store)                          \
    {                                                                      \
        const float xf = (xv) * wi_f;                                      \
        const float xg = (xv) * wi_g;                                      \
        const float xi = (xv) * wi_i;                                      \
        const float xo = (xv) * wi_o;                                      \
        const float sf = fmaf(to, wh_f, wh_f);                             \
        const float sg = fmaf(to, wh_g, wh_g);                             \
        const float si = fmaf(to, wh_i, wh_i);                             \
        const float so = fmaf(to, wh_o, wh_o);                             \
        const float hc = 0.5f * c;                                         \
        const float af = fmaf(tc, sf, xf);                                 \
        const float ag = fmaf(tc, sg, xg);                                 \
        const float ai = fmaf(tc, si, xi);                                 \
        const float ao = fmaf(tc, so, xo);                                 \
        const float tf = tanh_approx(af);                                  \
        const float tg = tanh_approx(ag);                                  \
        const float ti = tanh_approx(ai);                                  \
        const float to2 = tanh_approx(ao);                                 \
        (op)[(t_store) * LSTM_B] = hp;                                     \
        const float v   = fmaf(tf, hc, hc);                                \
        const float htg = 0.5f * tg;                                       \
        const float s   = v + htg;                                         \
        c = fmaf(ti, htg, s);                                              \
        const float tc2 = tanh_approx(c);                                  \
        const float sho = fmaf(to2, 0.5f, 0.5f);                           \
        hp = tc2 * sho;                                                    \
        tc = tc2;                                                          \
        to = to2;                                                          \
    }

    for (int t0 = 0; t0 < LSTM_T; t0 += 32) {
#pragma unroll
        for (int ph = 0; ph < 4; ++ph) {
#pragma unroll
            for (int u = 0; u < 8; ++u) {
                const int t = t0 + ph * 8 + u;
                // Pipelined store index: previous step (clamped at t==0; the
                // dummy 0.0 at op[0] is overwritten at t==1).
                const int ts = (t > 0) ? (t - 1) : 0;
                LSTM_STEP(tcA, toA, cA, hpA, xrA[ph * 8 + u], opA, ts)
                LSTM_STEP(tcB, toB, cB, hpB, xrB[ph * 8 + u], opB, ts)
            }
            // Reload this phase's buffers for t0+32 (clamped base at tail).
            {
                int tb = t0 + 32 + ph * 8;
                tb = (tb <= LSTM_T - 8) ? tb : (LSTM_T - 8);
                const float* qA = xpA + tb * LSTM_B;
                const float* qB = xpB + tb * LSTM_B;
#pragma unroll
                for (int u = 0; u < 8; ++u) xrA[ph * 8 + u] = qA[u * LSTM_B];
#pragma unroll
                for (int u = 0; u < 8; ++u) xrB[ph * 8 + u] = qB[u * LSTM_B];
            }
        }
    }
#undef LSTM_STEP

    // Final pending outputs (t = T-1), then h_n, c_n (tuple flattening order).
    opA[(LSTM_T - 1) * LSTM_B] = hpA;
    opB[(LSTM_T - 1) * LSTM_B] = hpB;
    if (out_size >= LSTM_T * LSTM_B + 2 * LSTM_B) {
        out[LSTM_T * LSTM_B + b]               = hpA;
        out[LSTM_T * LSTM_B + b + HB]          = hpB;
        out[LSTM_T * LSTM_B + LSTM_B + b]      = cA;
        out[LSTM_T * LSTM_B + LSTM_B + b + HB] = cB;
    }
}

extern "C" void kernel_launch(void* const* d_in, const int* in_sizes, int n_in,
                              void* d_out, int out_size) {
    const float* x    = (const float*)d_in[0];
    const float* h0   = (const float*)d_in[1];
    const float* c0   = (const float*)d_in[2];
    const float* w_ih = (const float*)d_in[3];
    const float* w_hh = (const float*)d_in[4];
    float* out = (float*)d_out;

    // 4096 threads, two chains each: 32 blocks x 128.
    const int threads = 128;
    const int blocks  = (LSTM_B / 2 + threads - 1) / threads;
    lstm_scalar_chain_kernel<<<blocks, threads>>>(x, h0, c0, w_ih, w_hh, out, out_size);
}